// round 4
// baseline (speedup 1.0000x reference)
#include <cuda_runtime.h>
#include <cstdint>

// TNorm: out[b, ((i0*8+i1)*8+i2)*8+i3] = g0[i0]*g1[i1]*g2[i2]*g3[i3], g=x[b].
// x: (16384,32) fp32 -> out: (16384,4096) fp32. 256 MiB pure write stream.
//
// R3 (45.3us, DRAM 63%): CTA-wide barriers + one 16KB group chain per CTA
// made store issue bursty; CTAs parked in wait_group while DRAM idled 37%.
// R4: warp-decoupled. Each warp owns a 4KB quarter-row, a private 4-deep
// smem ring, its own bulk_group chain; only __syncwarp. x row lives in one
// register/lane, factors via shuffles. 12 independent streams/SM.

#define BATCH      16384
#define ROW_FLOATS 4096
#define NT         128
#define NBUF       4          // 4KB x 4 per warp -> 3 groups in flight/warp
#define QFLOATS    1024       // floats per warp slice
#define QBYTES     4096
#define GRID_CTAS  (148 * 3)  // 64KB smem/CTA -> 3 CTAs/SM
#define SMEM_BYTES (4 * NBUF * QBYTES)

__global__ __launch_bounds__(NT)
void tnorm_warp_kernel(const float* __restrict__ x, float* __restrict__ out) {
    extern __shared__ float smem[];
    const int t = threadIdx.x;
    const int w = t >> 5;
    const int l = t & 31;
    float* wbuf = smem + w * (NBUF * QFLOATS);   // this warp's private ring

    // lane-invariant index pieces (see header decomposition)
    const int hi  = l >> 4;          // contributes to i1
    const int i2  = (l & 15) >> 1;
    const int i3b = (l & 1) * 4;

    uint64_t pol;   // streaming: output lines are write-once, evict first
    asm volatile("createpolicy.fractional.L2::evict_first.b64 %0, 1.0;" : "=l"(pol));

    int row = blockIdx.x;
    float gc = (row < BATCH) ? __ldg(x + (size_t)row * 32 + l) : 0.f;

    int it = 0;
    for (; row < BATCH; row += gridDim.x, ++it) {
        // prefetch next row's x element (hidden behind this iteration)
        const int nrow = row + gridDim.x;
        float gn = (nrow < BATCH) ? __ldg(x + (size_t)nrow * 32 + l) : 0.f;

        float* b = wbuf + (it & (NBUF - 1)) * QFLOATS;

        // buffer reuse guard: group issued NBUF iters ago must be smem-read done
        if (l == 0)
            asm volatile("cp.async.bulk.wait_group.read %0;" :: "n"(NBUF - 1) : "memory");
        __syncwarp();

        // gather all needed factors from the register-resident row
        const float g0a = __shfl_sync(0xffffffffu, gc, 2 * w);
        const float g0b = __shfl_sync(0xffffffffu, gc, 2 * w + 1);
        const float c2  = __shfl_sync(0xffffffffu, gc, 16 + i2);
        const float a0  = __shfl_sync(0xffffffffu, gc, 24 + i3b + 0);
        const float a1  = __shfl_sync(0xffffffffu, gc, 24 + i3b + 1);
        const float a2  = __shfl_sync(0xffffffffu, gc, 24 + i3b + 2);
        const float a3  = __shfl_sync(0xffffffffu, gc, 24 + i3b + 3);
        float p12[4];   // g1[2m+hi] * g2[i2], m = k & 3
        #pragma unroll
        for (int m = 0; m < 4; m++)
            p12[m] = __shfl_sync(0xffffffffu, gc, 8 + 2 * m + hi) * c2;

        #pragma unroll
        for (int k = 0; k < 8; k++) {
            const float s = (k < 4 ? g0a : g0b) * p12[k & 3];
            float4 v = make_float4(s * a0, s * a1, s * a2, s * a3);
            *reinterpret_cast<float4*>(b + k * 128 + l * 4) = v;  // conflict-free
        }
        __syncwarp();

        if (l == 0) {
            asm volatile("fence.proxy.async.shared::cta;" ::: "memory");
            const uint32_t saddr = (uint32_t)__cvta_generic_to_shared(b);
            float* dst = out + (size_t)row * ROW_FLOATS + w * QFLOATS;
            asm volatile(
                "cp.async.bulk.global.shared::cta.bulk_group.L2::cache_hint "
                "[%0], [%1], %2, %3;"
                :: "l"(dst), "r"(saddr), "n"(QBYTES), "l"(pol) : "memory");
            asm volatile("cp.async.bulk.commit_group;" ::: "memory");
        }
        gc = gn;
    }

    // drain before CTA exit deallocates smem
    if (l == 0)
        asm volatile("cp.async.bulk.wait_group.read 0;" ::: "memory");
    __syncwarp();
}

extern "C" void kernel_launch(void* const* d_in, const int* in_sizes, int n_in,
                              void* d_out, int out_size) {
    const float* x = (const float*)d_in[0];
    float* out = (float*)d_out;
    static bool attr_set = false;
    if (!attr_set) {
        cudaFuncSetAttribute(tnorm_warp_kernel,
                             cudaFuncAttributeMaxDynamicSharedMemorySize,
                             SMEM_BYTES);
        attr_set = true;
    }
    tnorm_warp_kernel<<<GRID_CTAS, NT, SMEM_BYTES>>>(x, out);
}